// round 1
// baseline (speedup 1.0000x reference)
#include <cuda_runtime.h>
#include <stdint.h>

#define NSEG 6
#define NC   512
#define NP   16384   // 128*128
#define BINS 16

// ---------------- scratch (__device__ globals, no allocation) ----------------
__device__ uint8_t g_meta[NSEG * NP];          // bits0-3: primary bin, bit4: extra(bin-1), bit5: masked
__device__ float   g_inv [NSEG * BINS];        // 1/denom per (seg,bin)
__device__ float   g_ys  [NSEG * NC * BINS];   // pooled features, [seg][c*16+k]
__device__ float   g_wA  [NSEG * 2048];
__device__ float   g_wB  [NSEG * 512];

// ---------------- kernel 1: mask + prefix scan + bin metadata ----------------
// grid <<<6, 256>>>, each thread owns 64 contiguous positions.
__global__ void k_scan(const int* __restrict__ parsing) {
    const int seg = blockIdx.x;
    const int tid = threadIdx.x;
    const int lane = tid & 31, wid = tid >> 5;
    const int* ps = parsing + seg * 65536;     // [256,256] plane

    const int base_p = tid * 64;
    uint64_t bits = 0;
    #pragma unroll
    for (int j = 0; j < 64; j++) {
        int p = base_p + j;
        int h = p >> 7, w = p & 127;
        // nearest resize 256->128: src = (2h, 2w)
        if (ps[h * 512 + w * 2] != 0) bits |= (1ull << j);
    }
    int cnt = __popcll(bits);

    // block exclusive scan over 256 per-thread counts
    __shared__ int warp_tot[8];
    __shared__ int warp_off[8];
    __shared__ int sL;
    int x = cnt;
    #pragma unroll
    for (int off = 1; off < 32; off <<= 1) {
        int y = __shfl_up_sync(0xffffffffu, x, off);
        if (lane >= off) x += y;
    }
    if (lane == 31) warp_tot[wid] = x;
    __syncthreads();
    if (tid < 8) {
        int s = 0;
        for (int i = 0; i < tid; i++) s += warp_tot[i];
        warp_off[tid] = s;
    }
    __syncthreads();
    int excl = warp_off[wid] + x - cnt;        // exclusive prefix of this thread
    if (tid == 255) sL = excl + cnt;
    __syncthreads();
    const int L = sL;

    if (tid < BINS) {
        int k = tid;
        int start = (k * L) / BINS;
        int end   = ((k + 1) * L + BINS - 1) / BINS;
        int denom = max(end - start, 1);
        g_inv[seg * BINS + k] = 1.0f / (float)denom;
    }

    uint8_t* mout = g_meta + seg * NP;
    int r = excl;
    #pragma unroll 4
    for (int j = 0; j < 64; j++) {
        uint8_t mb = 0;
        if ((bits >> j) & 1ull) {
            int k1 = (16 * (r + 1) - 1) / L;   // L>0 guaranteed whenever any bit set
            if (k1 > 15) k1 = 15;
            mb = (uint8_t)(32u | (unsigned)k1);
            // overlap: r also belongs to bin k1-1 (AdaptiveAvgPool1d ceil-end)
            if (k1 >= 1 && r == (k1 * L) / 16 && (k1 * L) % 16 != 0) mb |= 16u;
            r++;
        }
        mout[base_p + j] = mb;
    }
}

// ---------------- kernel 2: masked adaptive pooling (reads 201 MB of xs) -----
// grid (NC, NSEG), 256 threads. Running-bin accumulator + shared-bin flush.
__global__ void k_pool(const float* __restrict__ xs) {
    const int c = blockIdx.x, seg = blockIdx.y;
    const int tid = threadIdx.x;
    __shared__ float sbins[BINS];
    __shared__ float sinv [BINS];
    if (tid < BINS) {
        sbins[tid] = 0.0f;
        sinv[tid]  = g_inv[seg * BINS + tid];
    }
    __syncthreads();

    const float4* x4 = (const float4*)(xs + ((size_t)seg * NC + c) * NP);
    const uchar4* m4 = (const uchar4*)(g_meta + seg * NP);

    int   cur = -1;
    float acc = 0.0f;
    #pragma unroll 4
    for (int i = 0; i < 16; i++) {
        int idx = i * 256 + tid;               // coalesced
        float4 xv = x4[idx];
        uchar4 mv = m4[idx];
        float xa[4] = {xv.x, xv.y, xv.z, xv.w};
        unsigned ma[4] = {mv.x, mv.y, mv.z, mv.w};
        #pragma unroll
        for (int j = 0; j < 4; j++) {
            unsigned mm = ma[j];
            if (mm & 32u) {
                int k1 = (int)(mm & 15u);
                if (k1 != cur) {               // flush on bin change (rank monotone in p)
                    if (cur >= 0) atomicAdd(&sbins[cur], acc * sinv[cur]);
                    cur = k1; acc = 0.0f;
                }
                acc += xa[j];
                if (mm & 16u)                  // rare overlap into previous bin
                    atomicAdd(&sbins[k1 - 1], xa[j] * sinv[k1 - 1]);
            }
        }
    }
    if (cur >= 0) atomicAdd(&sbins[cur], acc * sinv[cur]);
    __syncthreads();
    if (tid < BINS)
        g_ys[((size_t)seg * NC + c) * BINS + tid] = sbins[tid];
}

// ---------------- generic GEMV: warp per row, float4 loads -------------------
template <int NDIM>
__global__ void k_gemv(const float* __restrict__ W, const float* __restrict__ xin,
                       const float* __restrict__ b, float* __restrict__ y,
                       int rows_per_seg, int x_seg_stride, int y_seg_stride) {
    const int gwarp = (blockIdx.x * blockDim.x + threadIdx.x) >> 5;
    const int lane  = threadIdx.x & 31;
    const int row   = gwarp;
    const int seg   = row / rows_per_seg;
    const int m     = row - seg * rows_per_seg;

    const float4* W4 = (const float4*)(W + (size_t)row * NDIM);
    const float4* x4 = (const float4*)(xin + (size_t)seg * x_seg_stride);

    float acc = 0.0f;
    #pragma unroll 4
    for (int i = lane; i < NDIM / 4; i += 32) {
        float4 w = W4[i];
        float4 v = x4[i];
        acc += w.x * v.x + w.y * v.y + w.z * v.z + w.w * v.w;
    }
    #pragma unroll
    for (int off = 16; off; off >>= 1) acc += __shfl_down_sync(0xffffffffu, acc, off);
    if (lane == 0) y[(size_t)seg * y_seg_stride + m] = acc + b[row];
}

// ---------------- final cascade: p1/p2/p3 on w0, per-segment block ----------
__global__ void k_final(const float* __restrict__ p1w, const float* __restrict__ p1b,
                        const float* __restrict__ p2w, const float* __restrict__ p2b,
                        const float* __restrict__ p3w, const float* __restrict__ p3b,
                        float* __restrict__ out) {
    const int seg = blockIdx.x;
    const int tid = threadIdx.x, lane = tid & 31, wid = tid >> 5; // 8 warps
    __shared__ float w0s[512], w1s[256], w2s[128];
    float* o = out + seg * 960;

    for (int i = tid; i < 512; i += 256) w0s[i] = o[i];   // w0 written by fcC
    __syncthreads();

    for (int m = wid; m < 256; m += 8) {                   // w1 = p1_w @ w0 + p1_b
        float acc = 0.0f;
        for (int n = lane; n < 512; n += 32) acc += p1w[m * 512 + n] * w0s[n];
        #pragma unroll
        for (int off = 16; off; off >>= 1) acc += __shfl_down_sync(0xffffffffu, acc, off);
        if (lane == 0) { float v = acc + p1b[m]; w1s[m] = v; o[512 + m] = v; }
    }
    __syncthreads();

    for (int m = wid; m < 128; m += 8) {                   // w2
        float acc = 0.0f;
        for (int n = lane; n < 256; n += 32) acc += p2w[m * 256 + n] * w1s[n];
        #pragma unroll
        for (int off = 16; off; off >>= 1) acc += __shfl_down_sync(0xffffffffu, acc, off);
        if (lane == 0) { float v = acc + p2b[m]; w2s[m] = v; o[768 + m] = v; }
    }
    __syncthreads();

    for (int m = wid; m < 64; m += 8) {                    // w3
        float acc = 0.0f;
        for (int n = lane; n < 128; n += 32) acc += p3w[m * 128 + n] * w2s[n];
        #pragma unroll
        for (int off = 16; off; off >>= 1) acc += __shfl_down_sync(0xffffffffu, acc, off);
        if (lane == 0) o[896 + m] = acc + p3b[m];
    }
}

// ---------------- launch ----------------------------------------------------
extern "C" void kernel_launch(void* const* d_in, const int* in_sizes, int n_in,
                              void* d_out, int out_size) {
    const float* xs      = (const float*)d_in[0];   // [6,1,512,128,128]
    const int*   parsing = (const int*)  d_in[1];   // [1,6,256,256]
    const float* fcA_w   = (const float*)d_in[2];   // [6,2048,8192]
    const float* fcA_b   = (const float*)d_in[3];   // [6,2048]
    const float* fcB_w   = (const float*)d_in[4];   // [6,512,2048]
    const float* fcB_b   = (const float*)d_in[5];   // [6,512]
    const float* fcC_w   = (const float*)d_in[6];   // [6,512,512]
    const float* fcC_b   = (const float*)d_in[7];   // [6,512]
    const float* p1_w    = (const float*)d_in[8];   // [256,512]
    const float* p1_b    = (const float*)d_in[9];
    const float* p2_w    = (const float*)d_in[10];  // [128,256]
    const float* p2_b    = (const float*)d_in[11];
    const float* p3_w    = (const float*)d_in[12];  // [64,128]
    const float* p3_b    = (const float*)d_in[13];
    float* out = (float*)d_out;                     // [6,1,960]

    float* ysp; cudaGetSymbolAddress((void**)&ysp, g_ys);
    float* wAp; cudaGetSymbolAddress((void**)&wAp, g_wA);
    float* wBp; cudaGetSymbolAddress((void**)&wBp, g_wB);

    // 1) mask + scan + bin metadata
    k_scan<<<NSEG, 256>>>(parsing);

    // 2) masked adaptive pooling over xs (201 MB)
    k_pool<<<dim3(NC, NSEG), 256>>>(xs);

    // 3) fcA: 6x[2048x8192] GEMV (402 MB) -> g_wA
    k_gemv<8192><<<(NSEG * 2048) / 8, 256>>>(fcA_w, ysp, fcA_b, wAp, 2048, NC * BINS, 2048);

    // 4) fcB: 6x[512x2048] -> g_wB
    k_gemv<2048><<<(NSEG * 512) / 8, 256>>>(fcB_w, wAp, fcB_b, wBp, 512, 2048, 512);

    // 5) fcC: 6x[512x512] -> out[seg*960 + 0..511] (w0)
    k_gemv<512><<<(NSEG * 512) / 8, 256>>>(fcC_w, wBp, fcC_b, out, 512, 512, 960);

    // 6) p1/p2/p3 cascade -> out[seg*960 + 512..959]
    k_final<<<NSEG, 256>>>(p1_w, p1_b, p2_w, p2_b, p3_w, p3_b, out);
}